// round 14
// baseline (speedup 1.0000x reference)
#include <cuda_runtime.h>
#include <cuda_bf16.h>
#include <cstdint>

// Problem constants
#define B_  2
#define L_  2048
#define DM_ 1024
#define E_  2048
#define N_  16
#define KC_ 4
#define R_  64
#define BL_ (B_ * L_)   // 4096
#define E2_ (2 * E_)    // 4096
#define SEG_ 4
#define SEGL_ (L_ / SEG_)   // 512

// ---------------- scratch (static device memory) ----------------------------
__device__ float g_xz  [BL_ * E2_];          // in_proj output (u_pre | z)
__device__ float g_u   [BL_ * E_];           // post conv+silu (tf32-rounded)
__device__ float g_xdbl[BL_ * 96];           // x_proj output (dt_low|B|C)
__device__ float g_xp  [4 * BL_ * 128];      // x_proj split-K partials
__device__ float g_xpw [128 * E_];           // x_proj_w padded (tf32)
__device__ float g_xn  [BL_ * DM_];          // rmsnorm out (tf32)
__device__ float g_wi  [E2_ * DM_];          // in_proj_w  (tf32)
__device__ float g_wo  [DM_ * E_];           // out_proj_w (tf32)
__device__ float g_y   [BL_ * E_];           // scan out (tf32)
__device__ float g_dt  [BL_ * E_];           // softplus(dt) from pass1
__device__ float2 g_seg[B_ * 256 * SEG_ * 128]; // per-segment (P, q)

// ---------------- PTX helpers -----------------------------------------------
__device__ __forceinline__ uint32_t smem_u32(const void* p) {
    return (uint32_t)__cvta_generic_to_shared(p);
}
__device__ __forceinline__ void cp_async16(uint32_t dst, const void* src) {
    asm volatile("cp.async.cg.shared.global [%0], [%1], 16;\n" :: "r"(dst), "l"(src));
}
#define CP_COMMIT() asm volatile("cp.async.commit_group;\n" ::: "memory")
#define CP_WAIT(n)  asm volatile("cp.async.wait_group %0;\n" :: "n"(n) : "memory")

#define LDSM4(r0, r1, r2, r3, addr) \
    asm volatile("ldmatrix.sync.aligned.m8n8.x4.shared.b16 {%0,%1,%2,%3}, [%4];" \
        : "=r"(r0), "=r"(r1), "=r"(r2), "=r"(r3) : "r"(addr))
#define LDSM2(r0, r1, addr) \
    asm volatile("ldmatrix.sync.aligned.m8n8.x2.shared.b16 {%0,%1}, [%2];" \
        : "=r"(r0), "=r"(r1) : "r"(addr))

#define MMATF32(c, a, b) \
    asm volatile("mma.sync.aligned.m16n8k8.row.col.f32.tf32.tf32.f32 " \
        "{%0,%1,%2,%3}, {%4,%5,%6,%7}, {%8,%9}, {%0,%1,%2,%3};" \
        : "+f"((c)[0]), "+f"((c)[1]), "+f"((c)[2]), "+f"((c)[3]) \
        : "r"((a)[0]), "r"((a)[1]), "r"((a)[2]), "r"((a)[3]), "r"((b)[0]), "r"((b)[1]))

__device__ __forceinline__ float tf32_round(float v) {
    float o;
    asm("cvt.rna.tf32.f32 %0, %1;" : "=f"(o) : "f"(v));
    return o;
}

// ---------------- fused prep: round wi, wo; pad+round xpw -------------------
#define NWI (E2_ * DM_ / 4)
#define NWO (DM_ * E_ / 4)
#define NXP (128 * E_ / 4)
__global__ void prep_kernel(const float* __restrict__ wi,
                            const float* __restrict__ wo,
                            const float* __restrict__ xp) {
    int i = blockIdx.x * 256 + threadIdx.x;
    float4 v;
    float4* dst;
    if (i < NWI) {
        v = ((const float4*)wi)[i];
        dst = ((float4*)g_wi) + i;
    } else if (i < NWI + NWO) {
        v = ((const float4*)wo)[i - NWI];
        dst = ((float4*)g_wo) + (i - NWI);
    } else {
        int j = i - NWI - NWO;
        int row = (j * 4) >> 11;
        v = (row < 96) ? ((const float4*)xp)[j] : make_float4(0.f, 0.f, 0.f, 0.f);
        dst = ((float4*)g_xpw) + j;
    }
    v.x = tf32_round(v.x); v.y = tf32_round(v.y);
    v.z = tf32_round(v.z); v.w = tf32_round(v.w);
    *dst = v;
}

// ---------------- RMSNorm -> tf32-rounded fp32, float4 ----------------------
__global__ void rmsnorm_kernel(const float* __restrict__ x,
                               const float* __restrict__ w) {
    int row = blockIdx.x;
    const float4* xr = (const float4*)(x + (size_t)row * DM_);
    float4 v = xr[threadIdx.x];
    float s = v.x * v.x + v.y * v.y + v.z * v.z + v.w * v.w;
    __shared__ float red[8];
    for (int o = 16; o; o >>= 1) s += __shfl_xor_sync(0xffffffffu, s, o);
    if ((threadIdx.x & 31) == 0) red[threadIdx.x >> 5] = s;
    __syncthreads();
    if (threadIdx.x < 8) {
        float t = red[threadIdx.x];
        for (int o = 4; o; o >>= 1) t += __shfl_xor_sync(0xffu, t, o);
        if (threadIdx.x == 0) red[0] = t;
    }
    __syncthreads();
    float inv = rsqrtf(red[0] * (1.f / DM_) + 1e-5f);
    float4 wv = ((const float4*)w)[threadIdx.x];
    float4 o;
    o.x = tf32_round(v.x * inv * wv.x);
    o.y = tf32_round(v.y * inv * wv.y);
    o.z = tf32_round(v.z * inv * wv.z);
    o.w = tf32_round(v.w * inv * wv.w);
    ((float4*)(g_xn + (size_t)row * DM_))[threadIdx.x] = o;
}

// ---------------- tf32 HMMA GEMM, 3-stage pipeline (R10-exact core) ---------
#define TTILE 16384
#define GEMM_SMEM (1024 + 6 * TTILE)

template <int MODE>
__global__ __launch_bounds__(256, 2) void gemm_tf32(
    const float* __restrict__ A, int lda,
    const float* __restrict__ B, int ldb,
    const float* __restrict__ resid, float* __restrict__ C, int ldc, int Ksplit) {
    extern __shared__ char smem[];
    uint32_t sb = smem_u32(smem);
    uint32_t tb0 = (sb + 1023u) & ~1023u;
    int tid = threadIdx.x, wid = tid >> 5, lid = tid & 31;
    int wm = wid >> 2, wn = wid & 3;

    int bm = blockIdx.y * 128, bn = blockIdx.x * 128;
    int kbeg = blockIdx.z * Ksplit;
    size_t coff = (size_t)blockIdx.z * gridDim.y * 128 * ldc;
    const int NC = Ksplit >> 5;

    auto load_tile = [&](uint32_t dst, const float* g, int row0, int ld, int k0) {
#pragma unroll
        for (int it = 0; it < 4; it++) {
            int idx = tid + it * 256;
            int r = idx >> 3, c16 = idx & 7;
            uint32_t off = (uint32_t)(r * 128 + ((c16 ^ (r & 7)) << 4));
            cp_async16(dst + off, g + (size_t)(row0 + r) * ld + k0 + c16 * 4);
        }
    };
    auto load_chunk = [&](int stage, int k0) {
        uint32_t tb = tb0 + stage * 2 * TTILE;
        load_tile(tb,         A, bm, lda, k0);
        load_tile(tb + TTILE, B, bn, ldb, k0);
        CP_COMMIT();
    };

    float acc[4][4][4];
#pragma unroll
    for (int i = 0; i < 4; i++)
#pragma unroll
        for (int j = 0; j < 4; j++)
#pragma unroll
            for (int q = 0; q < 4; q++) acc[i][j][q] = 0.f;

    load_chunk(0, kbeg);
    if (NC > 1) load_chunk(1, kbeg + 32);
    for (int ci = 0; ci < NC; ci++) {
        int s = ci % 3;
        if (ci + 2 < NC) {
            __syncthreads();
            load_chunk((ci + 2) % 3, kbeg + (ci + 2) * 32);
            CP_WAIT(2);
        } else if (ci + 1 < NC) {
            __syncthreads();
            CP_WAIT(1);
        } else {
            __syncthreads();
            CP_WAIT(0);
        }
        __syncthreads();
        uint32_t tA = tb0 + s * 2 * TTILE;
        uint32_t tB = tA + TTILE;
#pragma unroll
        for (int kk = 0; kk < 4; kk++) {
            uint32_t a[4][4];
#pragma unroll
            for (int i = 0; i < 4; i++) {
                int row = wm * 64 + i * 16 + (lid & 15);
                uint32_t chunk = (uint32_t)((kk * 2 + (lid >> 4)) ^ (row & 7));
                LDSM4(a[i][0], a[i][1], a[i][2], a[i][3],
                      tA + (uint32_t)(row * 128) + (chunk << 4));
            }
#pragma unroll
            for (int j = 0; j < 4; j++) {
                int row = wn * 32 + j * 8 + (lid & 7);
                uint32_t chunk = (uint32_t)((kk * 2 + ((lid >> 3) & 1)) ^ (row & 7));
                uint32_t b[2];
                LDSM2(b[0], b[1], tB + (uint32_t)(row * 128) + (chunk << 4));
#pragma unroll
                for (int i = 0; i < 4; i++) MMATF32(acc[i][j], a[i], b);
            }
        }
    }

    int r0 = bm + wm * 64 + (lid >> 2);
    int c0 = bn + wn * 32 + (lid & 3) * 2;
#pragma unroll
    for (int i = 0; i < 4; i++) {
#pragma unroll
        for (int j = 0; j < 4; j++) {
            int r = r0 + i * 16, c = c0 + j * 8;
            float2 v0 = {acc[i][j][0], acc[i][j][1]};
            float2 v1 = {acc[i][j][2], acc[i][j][3]};
            if (MODE == 2) {
                const float2 q0 = *(const float2*)(resid + (size_t)r * ldc + c);
                const float2 q1 = *(const float2*)(resid + (size_t)(r + 8) * ldc + c);
                v0.x += q0.x; v0.y += q0.y; v1.x += q1.x; v1.y += q1.y;
            }
            *(float2*)(C + coff + (size_t)r * ldc + c) = v0;
            *(float2*)(C + coff + (size_t)(r + 8) * ldc + c) = v1;
        }
    }
}

// ---------------- causal depthwise conv (K=4) + SiLU, 8 t per thread --------
__global__ void conv_silu_kernel(const float* __restrict__ cw,
                                 const float* __restrict__ cb) {
    int idx = blockIdx.x * 256 + threadIdx.x;
    int e4 = (idx & 511) * 4;
    int m0 = (idx >> 9) * 8;
    int t0 = m0 & (L_ - 1);
    float4 bias = *(const float4*)(cb + e4);
    float4 w0 = *(const float4*)(cw + (size_t)(e4 + 0) * 4);
    float4 w1 = *(const float4*)(cw + (size_t)(e4 + 1) * 4);
    float4 w2 = *(const float4*)(cw + (size_t)(e4 + 2) * 4);
    float4 w3 = *(const float4*)(cw + (size_t)(e4 + 3) * 4);
    const float* wp0 = (const float*)&w0;
    const float* wp1 = (const float*)&w1;
    const float* wp2 = (const float*)&w2;
    const float* wp3 = (const float*)&w3;

    float4 v[11];
#pragma unroll
    for (int i = 0; i < 11; i++) {
        int dt = i - 3;
        if (t0 + dt >= 0)
            v[i] = *(const float4*)(g_xz + (size_t)(m0 + dt) * E2_ + e4);
        else
            v[i] = make_float4(0.f, 0.f, 0.f, 0.f);
    }
#pragma unroll
    for (int j = 0; j < 8; j++) {
        float4 acc = bias;
#pragma unroll
        for (int k = 0; k < KC_; k++) {
            float4 q = v[j + k];
            acc.x = fmaf(wp0[k], q.x, acc.x);
            acc.y = fmaf(wp1[k], q.y, acc.y);
            acc.z = fmaf(wp2[k], q.z, acc.z);
            acc.w = fmaf(wp3[k], q.w, acc.w);
        }
        acc.x = tf32_round(acc.x / (1.f + __expf(-acc.x)));
        acc.y = tf32_round(acc.y / (1.f + __expf(-acc.y)));
        acc.z = tf32_round(acc.z / (1.f + __expf(-acc.z)));
        acc.w = tf32_round(acc.w / (1.f + __expf(-acc.w)));
        *(float4*)(g_u + (size_t)(m0 + j) * E_ + e4) = acc;
    }
}

// ---------------- xproj reduce: sum 4 padded partials -> [BL][96] -----------
__global__ void xproj_reduce_kernel() {
    int i = blockIdx.x * 256 + threadIdx.x;
    int r = i / 96, c = i - r * 96;
    const size_t S = (size_t)BL_ * 128;
    size_t p = (size_t)r * 128 + c;
    g_xdbl[i] = g_xp[p] + g_xp[p + S] + g_xp[p + 2 * S] + g_xp[p + 3 * S];
}

// ---------------- scan pass 1: per-segment (P, q) + dt -----------------------
__global__ __launch_bounds__(128) void scan_pass1(const float* __restrict__ A_log,
                                                  const float* __restrict__ Wdt,
                                                  const float* __restrict__ bdt) {
    __shared__ float w[8][64], db[8];
    __shared__ float xd[2][32][84];   // cols 0..79 (dt_low | B)
    __shared__ float su[2][32][12];
    __shared__ float dtv[32][9];

    int bx = blockIdx.x;
    int s  = bx & 3;
    int eg = (bx >> 2) & 255;
    int b  = bx >> 10;
    int e0 = eg * 8;
    int tbase = s * SEGL_;
    int tid = threadIdx.x;
    int n = tid & 15, c = tid >> 4;
    int e = e0 + c;

    for (int i = tid; i < 8 * 64; i += 128)
        w[i >> 6][i & 63] = Wdt[(size_t)(e0 + (i >> 6)) * R_ + (i & 63)];
    if (tid < 8) db[tid] = bdt[e0 + tid];

    float a = -__expf(A_log[e * N_ + n]);
    float h = 0.f, P = 1.f;

    auto prefetch = [&](int st, int t0) {
        int m0 = b * L_ + tbase + t0;
#pragma unroll
        for (int it = 0; it < 5; it++) {      // 640 float4: 32 rows x 20
            int idx = tid + it * 128;
            int r = idx / 20, c4 = (idx % 20) * 4;
            cp_async16(smem_u32(&xd[st][r][c4]),
                       g_xdbl + (size_t)(m0 + r) * 96 + c4);
        }
        if (tid < 64) {
            int r = tid >> 1, hf = (tid & 1) * 4;
            cp_async16(smem_u32(&su[st][r][hf]),
                       g_u + (size_t)(m0 + r) * E_ + e0 + hf);
        }
        CP_COMMIT();
    };

    prefetch(0, 0);
    for (int t0 = 0; t0 < SEGL_; t0 += 32) {
        int st = (t0 >> 5) & 1;
        if (t0 + 32 < SEGL_) { prefetch(st ^ 1, t0 + 32); CP_WAIT(1); }
        else                 { CP_WAIT(0); }
        __syncthreads();

        {   // fused dt projection + softplus
            int tt = tid & 31, c2 = tid >> 5;
            float a0 = db[c2], a1 = db[c2 + 4];
#pragma unroll
            for (int k = 0; k < 64; k++) {
                float xv = xd[st][tt][k];
                a0 = fmaf(xv, w[c2][k], a0);
                a1 = fmaf(xv, w[c2 + 4][k], a1);
            }
            dtv[tt][c2]     = (a0 > 20.f) ? a0 : log1pf(__expf(a0));
            dtv[tt][c2 + 4] = (a1 > 20.f) ? a1 : log1pf(__expf(a1));
        }
        __syncthreads();

        // recurrence + running product
#pragma unroll
        for (int tt = 0; tt < 32; tt++) {
            float d = dtv[tt][c];
            float dA = __expf(d * a);
            float xv = d * su[st][tt][c] * xd[st][tt][64 + n];
            h = fmaf(h, dA, xv);
            P *= dA;
        }
        // persist dt for pass 2
#pragma unroll
        for (int r = 0; r < 2; r++) {
            int idx = tid + r * 128;
            int tt = idx >> 3, cc = idx & 7;
            g_dt[(size_t)(b * L_ + tbase + t0 + tt) * E_ + e0 + cc] = dtv[tt][cc];
        }
        __syncthreads();
    }
    g_seg[(size_t)bx * 128 + tid] = make_float2(P, h);
}

// ---------------- scan pass 2: h0-corrected recurrence + y ------------------
__global__ __launch_bounds__(128) void scan_pass2(const float* __restrict__ A_log,
                                                  const float* __restrict__ Dp) {
    __shared__ float sd[8];
    __shared__ float bc[2][32][36];    // cols 64..95 (B | C)
    __shared__ float su[2][32][12], sz[2][32][12], sdt[2][32][12];
    __shared__ float hs[32][129];

    int bx = blockIdx.x;
    int s  = bx & 3;
    int eg = (bx >> 2) & 255;
    int b  = bx >> 10;
    int e0 = eg * 8;
    int tbase = s * SEGL_;
    int tid = threadIdx.x;
    int n = tid & 15, c = tid >> 4;
    int e = e0 + c;

    if (tid < 8) sd[tid] = Dp[e0 + tid];
    float a = -__expf(A_log[e * N_ + n]);

    // fold preceding segments' (P, q) into h0
    float h = 0.f;
    int segbase = ((b * 256 + eg) * 4) * 128 + tid;
    for (int j = 0; j < s; j++) {
        float2 pq = g_seg[segbase + j * 128];
        h = h * pq.x + pq.y;
    }

    auto prefetch = [&](int st, int t0) {
        int m0 = b * L_ + tbase + t0;
#pragma unroll
        for (int it = 0; it < 2; it++) {     // 256 float4: cols 64..95
            int idx = tid + it * 128;
            int r = idx >> 3, c4 = (idx & 7) * 4;
            cp_async16(smem_u32(&bc[st][r][c4]),
                       g_xdbl + (size_t)(m0 + r) * 96 + 64 + c4);
        }
#pragma unroll
        for (int it = 0; it < 2; it++) {     // 192 float4: u, z, dt slices
            int idx = tid + it * 128;
            if (idx < 192) {
                int which = idx / 64, wi = idx - which * 64;
                int r = wi >> 1, hf = (wi & 1) * 4;
                if (which == 0)
                    cp_async16(smem_u32(&su[st][r][hf]),
                               g_u + (size_t)(m0 + r) * E_ + e0 + hf);
                else if (which == 1)
                    cp_async16(smem_u32(&sz[st][r][hf]),
                               g_xz + (size_t)(m0 + r) * E2_ + E_ + e0 + hf);
                else
                    cp_async16(smem_u32(&sdt[st][r][hf]),
                               g_dt + (size_t)(m0 + r) * E_ + e0 + hf);
            }
        }
        CP_COMMIT();
    };

    prefetch(0, 0);
    for (int t0 = 0; t0 < SEGL_; t0 += 32) {
        int st = (t0 >> 5) & 1;
        if (t0 + 32 < SEGL_) { prefetch(st ^ 1, t0 + 32); CP_WAIT(1); }
        else                 { CP_WAIT(0); }
        __syncthreads();

        // recurrence with stored dt
#pragma unroll
        for (int tt = 0; tt < 32; tt++) {
            float d = sdt[st][tt][c];
            float dA = __expf(d * a);
            float xv = d * su[st][tt][c] * bc[st][tt][n];
            h = fmaf(h, dA, xv);
            hs[tt][tid] = h;
        }
        __syncthreads();

        // C-reduction + D-skip + silu(z) gate
#pragma unroll
        for (int r = 0; r < 2; r++) {
            int idx = tid + r * 128;
            int tt = idx >> 3, cc = idx & 7;
            float y = 0.f;
#pragma unroll
            for (int q = 0; q < 16; q++)
                y = fmaf(hs[tt][cc * 16 + q], bc[st][tt][16 + q], y);
            float uv = su[st][tt][cc];
            float zv = sz[st][tt][cc];
            float yv = fmaf(uv, sd[cc], y);
            yv = yv * (zv / (1.f + __expf(-zv)));
            g_y[(size_t)(b * L_ + tbase + t0 + tt) * E_ + e0 + cc] = tf32_round(yv);
        }
        __syncthreads();
    }
}

// ---------------- launch ----------------------------------------------------
extern "C" void kernel_launch(void* const* d_in, const int* in_sizes, int n_in,
                              void* d_out, int out_size) {
    const float* x         = (const float*)d_in[0];
    const float* norm_w    = (const float*)d_in[1];
    const float* in_proj_w = (const float*)d_in[2];
    const float* conv_w    = (const float*)d_in[3];
    const float* conv_b    = (const float*)d_in[4];
    const float* x_proj_w  = (const float*)d_in[5];
    const float* dt_proj_w = (const float*)d_in[6];
    const float* dt_proj_b = (const float*)d_in[7];
    const float* A_log     = (const float*)d_in[8];
    const float* Dp        = (const float*)d_in[9];
    const float* out_proj_w= (const float*)d_in[10];
    float* out = (float*)d_out;

    float *p_xz, *p_xn, *p_wi, *p_wo, *p_y, *p_u, *p_xpw, *p_xp;
    cudaGetSymbolAddress((void**)&p_xz,  g_xz);
    cudaGetSymbolAddress((void**)&p_xn,  g_xn);
    cudaGetSymbolAddress((void**)&p_wi,  g_wi);
    cudaGetSymbolAddress((void**)&p_wo,  g_wo);
    cudaGetSymbolAddress((void**)&p_y,   g_y);
    cudaGetSymbolAddress((void**)&p_u,   g_u);
    cudaGetSymbolAddress((void**)&p_xpw, g_xpw);
    cudaGetSymbolAddress((void**)&p_xp,  g_xp);

    cudaFuncSetAttribute(gemm_tf32<0>, cudaFuncAttributeMaxDynamicSharedMemorySize, GEMM_SMEM);
    cudaFuncSetAttribute(gemm_tf32<2>, cudaFuncAttributeMaxDynamicSharedMemorySize, GEMM_SMEM);

    // 0) fused weight prep
    prep_kernel<<<(NWI + NWO + NXP) / 256, 256>>>(in_proj_w, out_proj_w, x_proj_w);
    // 1) RMSNorm
    rmsnorm_kernel<<<BL_, 256>>>(x, norm_w);
    // 2) in_proj
    gemm_tf32<0><<<dim3(E2_ / 128, BL_ / 128, 1), 256, GEMM_SMEM>>>(
        p_xn, DM_, p_wi, DM_, nullptr, p_xz, E2_, DM_);
    // 3) conv + SiLU
    conv_silu_kernel<<<(BL_ / 8 * 512) / 256, 256>>>(conv_w, conv_b);
    // 4) x_proj (split-K x4) + reduce
    gemm_tf32<0><<<dim3(1, BL_ / 128, 4), 256, GEMM_SMEM>>>(
        p_u, E_, p_xpw, E_, nullptr, p_xp, 128, E_ / 4);
    xproj_reduce_kernel<<<(BL_ * 96) / 256, 256>>>();
    // 5) scan pass 1 (segment summaries + dt)
    scan_pass1<<<B_ * 256 * SEG_, 128>>>(A_log, dt_proj_w, dt_proj_b);
    // 6) scan pass 2 (corrected recurrence + y)
    scan_pass2<<<B_ * 256 * SEG_, 128>>>(A_log, Dp);
    // 7) out_proj + residual
    gemm_tf32<2><<<dim3(DM_ / 128, BL_ / 128, 1), 256, GEMM_SMEM>>>(
        p_y, E_, p_wo, E_, x, out, DM_, E_);
}

// round 16
// speedup vs baseline: 1.6212x; 1.6212x over previous
#include <cuda_runtime.h>
#include <cuda_bf16.h>
#include <cstdint>

// Problem constants
#define B_  2
#define L_  2048
#define DM_ 1024
#define E_  2048
#define N_  16
#define KC_ 4
#define R_  64
#define BL_ (B_ * L_)   // 4096
#define E2_ (2 * E_)    // 4096

// ---------------- scratch (static device memory) ----------------------------
__device__ float g_xz  [BL_ * E2_];          // in_proj output (u_pre | z)
__device__ float g_u   [BL_ * E_];           // post conv+silu (tf32-rounded)
__device__ float g_xdbl[BL_ * 96];           // x_proj output (dt_low|B|C)
__device__ float g_xp  [4 * BL_ * 128];      // x_proj split-K partials (padded N=128)
__device__ float g_xpw [128 * E_];           // x_proj_w padded to 128 rows (tf32)
__device__ float g_xn  [BL_ * DM_];          // rmsnorm out (tf32-rounded fp32)
__device__ float g_wi  [E2_ * DM_];          // in_proj_w  (tf32)
__device__ float g_wo  [DM_ * E_];           // out_proj_w (tf32)
__device__ float g_y   [BL_ * E_];           // scan out (tf32)

// ---------------- PTX helpers -----------------------------------------------
__device__ __forceinline__ uint32_t smem_u32(const void* p) {
    return (uint32_t)__cvta_generic_to_shared(p);
}
__device__ __forceinline__ void cp_async16(uint32_t dst, const void* src) {
    asm volatile("cp.async.cg.shared.global [%0], [%1], 16;\n" :: "r"(dst), "l"(src));
}
#define CP_COMMIT() asm volatile("cp.async.commit_group;\n" ::: "memory")
#define CP_WAIT(n)  asm volatile("cp.async.wait_group %0;\n" :: "n"(n) : "memory")

#define LDSM4(r0, r1, r2, r3, addr) \
    asm volatile("ldmatrix.sync.aligned.m8n8.x4.shared.b16 {%0,%1,%2,%3}, [%4];" \
        : "=r"(r0), "=r"(r1), "=r"(r2), "=r"(r3) : "r"(addr))
#define LDSM2(r0, r1, addr) \
    asm volatile("ldmatrix.sync.aligned.m8n8.x2.shared.b16 {%0,%1}, [%2];" \
        : "=r"(r0), "=r"(r1) : "r"(addr))

#define MMATF32(c, a, b) \
    asm volatile("mma.sync.aligned.m16n8k8.row.col.f32.tf32.tf32.f32 " \
        "{%0,%1,%2,%3}, {%4,%5,%6,%7}, {%8,%9}, {%0,%1,%2,%3};" \
        : "+f"((c)[0]), "+f"((c)[1]), "+f"((c)[2]), "+f"((c)[3]) \
        : "r"((a)[0]), "r"((a)[1]), "r"((a)[2]), "r"((a)[3]), "r"((b)[0]), "r"((b)[1]))

__device__ __forceinline__ float tf32_round(float v) {
    float o;
    asm("cvt.rna.tf32.f32 %0, %1;" : "=f"(o) : "f"(v));
    return o;
}

// ---------------- fused prep: round wi, wo; pad+round xpw -------------------
#define NWI (E2_ * DM_ / 4)
#define NWO (DM_ * E_ / 4)
#define NXP (128 * E_ / 4)
__global__ void prep_kernel(const float* __restrict__ wi,
                            const float* __restrict__ wo,
                            const float* __restrict__ xp) {
    int i = blockIdx.x * 256 + threadIdx.x;
    float4 v;
    float4* dst;
    if (i < NWI) {
        v = ((const float4*)wi)[i];
        dst = ((float4*)g_wi) + i;
    } else if (i < NWI + NWO) {
        v = ((const float4*)wo)[i - NWI];
        dst = ((float4*)g_wo) + (i - NWI);
    } else {
        int j = i - NWI - NWO;
        int row = (j * 4) >> 11;
        v = (row < 96) ? ((const float4*)xp)[j] : make_float4(0.f, 0.f, 0.f, 0.f);
        dst = ((float4*)g_xpw) + j;
    }
    v.x = tf32_round(v.x); v.y = tf32_round(v.y);
    v.z = tf32_round(v.z); v.w = tf32_round(v.w);
    *dst = v;
}

// ---------------- RMSNorm -> tf32-rounded fp32, float4 ----------------------
__global__ void rmsnorm_kernel(const float* __restrict__ x,
                               const float* __restrict__ w) {
    int row = blockIdx.x;
    const float4* xr = (const float4*)(x + (size_t)row * DM_);
    float4 v = xr[threadIdx.x];
    float s = v.x * v.x + v.y * v.y + v.z * v.z + v.w * v.w;
    __shared__ float red[8];
    for (int o = 16; o; o >>= 1) s += __shfl_xor_sync(0xffffffffu, s, o);
    if ((threadIdx.x & 31) == 0) red[threadIdx.x >> 5] = s;
    __syncthreads();
    if (threadIdx.x < 8) {
        float t = red[threadIdx.x];
        for (int o = 4; o; o >>= 1) t += __shfl_xor_sync(0xffu, t, o);
        if (threadIdx.x == 0) red[0] = t;
    }
    __syncthreads();
    float inv = rsqrtf(red[0] * (1.f / DM_) + 1e-5f);
    float4 wv = ((const float4*)w)[threadIdx.x];
    float4 o;
    o.x = tf32_round(v.x * inv * wv.x);
    o.y = tf32_round(v.y * inv * wv.y);
    o.z = tf32_round(v.z * inv * wv.z);
    o.w = tf32_round(v.w * inv * wv.w);
    ((float4*)(g_xn + (size_t)row * DM_))[threadIdx.x] = o;
}

// ---------------- tf32 HMMA GEMM, 3-stage cp.async pipeline (R10 core) ------
#define TTILE 16384
#define GEMM_SMEM (1024 + 6 * TTILE)

template <int MODE>
__global__ __launch_bounds__(256, 2) void gemm_tf32(
    const float* __restrict__ A, int lda,
    const float* __restrict__ B, int ldb,
    const float* __restrict__ resid, float* __restrict__ C, int ldc, int Ksplit) {
    extern __shared__ char smem[];
    uint32_t sb = smem_u32(smem);
    uint32_t tb0 = (sb + 1023u) & ~1023u;
    int tid = threadIdx.x, wid = tid >> 5, lid = tid & 31;
    int wm = wid >> 2, wn = wid & 3;

    int bm = blockIdx.y * 128, bn = blockIdx.x * 128;
    int kbeg = blockIdx.z * Ksplit;
    size_t coff = (size_t)blockIdx.z * gridDim.y * 128 * ldc;
    const int NC = Ksplit >> 5;

    auto load_tile = [&](uint32_t dst, const float* g, int row0, int ld, int k0) {
#pragma unroll
        for (int it = 0; it < 4; it++) {
            int idx = tid + it * 256;
            int r = idx >> 3, c16 = idx & 7;
            uint32_t off = (uint32_t)(r * 128 + ((c16 ^ (r & 7)) << 4));
            cp_async16(dst + off, g + (size_t)(row0 + r) * ld + k0 + c16 * 4);
        }
    };
    auto load_chunk = [&](int stage, int k0) {
        uint32_t tb = tb0 + stage * 2 * TTILE;
        load_tile(tb,         A, bm, lda, k0);
        load_tile(tb + TTILE, B, bn, ldb, k0);
        CP_COMMIT();
    };

    float acc[4][4][4];
#pragma unroll
    for (int i = 0; i < 4; i++)
#pragma unroll
        for (int j = 0; j < 4; j++)
#pragma unroll
            for (int q = 0; q < 4; q++) acc[i][j][q] = 0.f;

    load_chunk(0, kbeg);
    if (NC > 1) load_chunk(1, kbeg + 32);
    for (int ci = 0; ci < NC; ci++) {
        int s = ci % 3;
        if (ci + 2 < NC) {
            __syncthreads();
            load_chunk((ci + 2) % 3, kbeg + (ci + 2) * 32);
            CP_WAIT(2);
        } else if (ci + 1 < NC) {
            __syncthreads();
            CP_WAIT(1);
        } else {
            __syncthreads();
            CP_WAIT(0);
        }
        __syncthreads();
        uint32_t tA = tb0 + s * 2 * TTILE;
        uint32_t tB = tA + TTILE;
#pragma unroll
        for (int kk = 0; kk < 4; kk++) {
            uint32_t a[4][4];
#pragma unroll
            for (int i = 0; i < 4; i++) {
                int row = wm * 64 + i * 16 + (lid & 15);
                uint32_t chunk = (uint32_t)((kk * 2 + (lid >> 4)) ^ (row & 7));
                LDSM4(a[i][0], a[i][1], a[i][2], a[i][3],
                      tA + (uint32_t)(row * 128) + (chunk << 4));
            }
#pragma unroll
            for (int j = 0; j < 4; j++) {
                int row = wn * 32 + j * 8 + (lid & 7);
                uint32_t chunk = (uint32_t)((kk * 2 + ((lid >> 3) & 1)) ^ (row & 7));
                uint32_t b[2];
                LDSM2(b[0], b[1], tB + (uint32_t)(row * 128) + (chunk << 4));
#pragma unroll
                for (int i = 0; i < 4; i++) MMATF32(acc[i][j], a[i], b);
            }
        }
    }

    int r0 = bm + wm * 64 + (lid >> 2);
    int c0 = bn + wn * 32 + (lid & 3) * 2;
#pragma unroll
    for (int i = 0; i < 4; i++) {
#pragma unroll
        for (int j = 0; j < 4; j++) {
            int r = r0 + i * 16, c = c0 + j * 8;
            float2 v0 = {acc[i][j][0], acc[i][j][1]};
            float2 v1 = {acc[i][j][2], acc[i][j][3]};
            if (MODE == 2) {
                const float2 q0 = *(const float2*)(resid + (size_t)r * ldc + c);
                const float2 q1 = *(const float2*)(resid + (size_t)(r + 8) * ldc + c);
                v0.x += q0.x; v0.y += q0.y; v1.x += q1.x; v1.y += q1.y;
            }
            *(float2*)(C + coff + (size_t)r * ldc + c) = v0;
            *(float2*)(C + coff + (size_t)(r + 8) * ldc + c) = v1;
        }
    }
}

// ---------------- causal depthwise conv (K=4) + SiLU, 8 t per thread --------
__global__ void conv_silu_kernel(const float* __restrict__ cw,
                                 const float* __restrict__ cb) {
    int idx = blockIdx.x * 256 + threadIdx.x;
    int e4 = (idx & 511) * 4;
    int m0 = (idx >> 9) * 8;
    int t0 = m0 & (L_ - 1);
    float4 bias = *(const float4*)(cb + e4);
    float4 w0 = *(const float4*)(cw + (size_t)(e4 + 0) * 4);
    float4 w1 = *(const float4*)(cw + (size_t)(e4 + 1) * 4);
    float4 w2 = *(const float4*)(cw + (size_t)(e4 + 2) * 4);
    float4 w3 = *(const float4*)(cw + (size_t)(e4 + 3) * 4);
    const float* wp0 = (const float*)&w0;
    const float* wp1 = (const float*)&w1;
    const float* wp2 = (const float*)&w2;
    const float* wp3 = (const float*)&w3;

    float4 v[11];
#pragma unroll
    for (int i = 0; i < 11; i++) {
        int dt = i - 3;
        if (t0 + dt >= 0)
            v[i] = *(const float4*)(g_xz + (size_t)(m0 + dt) * E2_ + e4);
        else
            v[i] = make_float4(0.f, 0.f, 0.f, 0.f);
    }
#pragma unroll
    for (int j = 0; j < 8; j++) {
        float4 acc = bias;
#pragma unroll
        for (int k = 0; k < KC_; k++) {
            float4 q = v[j + k];
            acc.x = fmaf(wp0[k], q.x, acc.x);
            acc.y = fmaf(wp1[k], q.y, acc.y);
            acc.z = fmaf(wp2[k], q.z, acc.z);
            acc.w = fmaf(wp3[k], q.w, acc.w);
        }
        acc.x = tf32_round(acc.x / (1.f + __expf(-acc.x)));
        acc.y = tf32_round(acc.y / (1.f + __expf(-acc.y)));
        acc.z = tf32_round(acc.z / (1.f + __expf(-acc.z)));
        acc.w = tf32_round(acc.w / (1.f + __expf(-acc.w)));
        *(float4*)(g_u + (size_t)(m0 + j) * E_ + e4) = acc;
    }
}

// ---------------- xproj reduce: sum 4 padded partials -> [BL][96] -----------
__global__ void xproj_reduce_kernel() {
    int i = blockIdx.x * 256 + threadIdx.x;
    int r = i / 96, c = i - r * 96;
    const size_t S = (size_t)BL_ * 128;
    size_t p = (size_t)r * 128 + c;
    g_xdbl[i] = g_xp[p] + g_xp[p + S] + g_xp[p + 2 * S] + g_xp[p + 3 * S];
}

// ---------------- selective scan + fused dt projection (R10 form) -----------
struct ScanSmem {
    float w[8][64];           // dt_proj_w rows for this block's 8 channels
    float db[8], d[8];
    float xd[2][32][100];     // g_xdbl rows (96 cols, pad 100)
    float u[2][32][12];       // g_u slice (8 cols, pad 12)
    float z[2][32][12];       // z slice
    float dt[32][9];
    float h[32][129];
};
#define SCAN_SMEM ((int)sizeof(ScanSmem))

__global__ __launch_bounds__(128) void scan_kernel(const float* __restrict__ A_log,
                                                   const float* __restrict__ Dp,
                                                   const float* __restrict__ Wdt,
                                                   const float* __restrict__ bdt) {
    extern __shared__ char sraw[];
    ScanSmem* ss = (ScanSmem*)sraw;
    const int CH = 8;
    int b  = blockIdx.x / (E_ / CH);
    int e0 = (blockIdx.x % (E_ / CH)) * CH;
    int tid = threadIdx.x;
    int n = tid & 15, c = tid >> 4;
    int e = e0 + c;

    for (int i = tid; i < CH * 64; i += 128)
        ss->w[i >> 6][i & 63] = Wdt[(size_t)(e0 + (i >> 6)) * R_ + (i & 63)];
    if (tid < CH) { ss->db[tid] = bdt[e0 + tid]; ss->d[tid] = Dp[e0 + tid]; }

    float a = -__expf(A_log[e * N_ + n]);
    float h = 0.f;

    auto prefetch = [&](int st, int t0) {
        int m0 = b * L_ + t0;
#pragma unroll
        for (int it = 0; it < 6; it++) {
            int idx = tid + it * 128;
            int r = idx / 24, c4 = (idx % 24) * 4;
            cp_async16(smem_u32(&ss->xd[st][r][c4]),
                       g_xdbl + (size_t)(m0 + r) * 96 + c4);
        }
        if (tid < 64) {
            int r = tid >> 1, hf = (tid & 1) * 4;
            cp_async16(smem_u32(&ss->u[st][r][hf]),
                       g_u + (size_t)(m0 + r) * E_ + e0 + hf);
        } else {
            int q = tid - 64;
            int r = q >> 1, hf = (q & 1) * 4;
            cp_async16(smem_u32(&ss->z[st][r][hf]),
                       g_xz + (size_t)(m0 + r) * E2_ + E_ + e0 + hf);
        }
        CP_COMMIT();
    };

    prefetch(0, 0);
    for (int t0 = 0; t0 < L_; t0 += 32) {
        int st = (t0 >> 5) & 1;
        if (t0 + 32 < L_) { prefetch(st ^ 1, t0 + 32); CP_WAIT(1); }
        else              { CP_WAIT(0); }
        __syncthreads();

        // fused dt projection + softplus
        {
            int tt = tid & 31, c2 = tid >> 5;
            float a0 = ss->db[c2], a1 = ss->db[c2 + 4];
#pragma unroll
            for (int k = 0; k < 64; k++) {
                float xv = ss->xd[st][tt][k];
                a0 = fmaf(xv, ss->w[c2][k], a0);
                a1 = fmaf(xv, ss->w[c2 + 4][k], a1);
            }
            ss->dt[tt][c2]     = (a0 > 20.f) ? a0 : log1pf(__expf(a0));
            ss->dt[tt][c2 + 4] = (a1 > 20.f) ? a1 : log1pf(__expf(a1));
        }
        __syncthreads();

        // recurrence
        float hh = h;
#pragma unroll
        for (int tt = 0; tt < 32; tt++) {
            float dtv = ss->dt[tt][c];
            float dA = __expf(dtv * a);
            float xv = dtv * ss->u[st][tt][c] * ss->xd[st][tt][64 + n];
            hh = fmaf(hh, dA, xv);
            ss->h[tt][tid] = hh;
        }
        h = hh;
        __syncthreads();

        // C-reduction + D-skip + silu(z) gate
#pragma unroll
        for (int r = 0; r < 2; r++) {
            int idx = tid + r * 128;
            int tt = idx >> 3, cc = idx & 7;
            float y = 0.f;
#pragma unroll
            for (int q = 0; q < 16; q++)
                y = fmaf(ss->h[tt][cc * 16 + q], ss->xd[st][tt][80 + q], y);
            float uv = ss->u[st][tt][cc];
            float zv = ss->z[st][tt][cc];
            float yv = fmaf(uv, ss->d[cc], y);
            yv = yv * (zv / (1.f + __expf(-zv)));
            g_y[(size_t)(b * L_ + t0 + tt) * E_ + e0 + cc] = tf32_round(yv);
        }
        __syncthreads();
    }
}

// ---------------- launch ----------------------------------------------------
extern "C" void kernel_launch(void* const* d_in, const int* in_sizes, int n_in,
                              void* d_out, int out_size) {
    const float* x         = (const float*)d_in[0];
    const float* norm_w    = (const float*)d_in[1];
    const float* in_proj_w = (const float*)d_in[2];
    const float* conv_w    = (const float*)d_in[3];
    const float* conv_b    = (const float*)d_in[4];
    const float* x_proj_w  = (const float*)d_in[5];
    const float* dt_proj_w = (const float*)d_in[6];
    const float* dt_proj_b = (const float*)d_in[7];
    const float* A_log     = (const float*)d_in[8];
    const float* Dp        = (const float*)d_in[9];
    const float* out_proj_w= (const float*)d_in[10];
    float* out = (float*)d_out;

    float *p_xz, *p_xn, *p_wi, *p_wo, *p_y, *p_u, *p_xpw, *p_xp;
    cudaGetSymbolAddress((void**)&p_xz,  g_xz);
    cudaGetSymbolAddress((void**)&p_xn,  g_xn);
    cudaGetSymbolAddress((void**)&p_wi,  g_wi);
    cudaGetSymbolAddress((void**)&p_wo,  g_wo);
    cudaGetSymbolAddress((void**)&p_y,   g_y);
    cudaGetSymbolAddress((void**)&p_u,   g_u);
    cudaGetSymbolAddress((void**)&p_xpw, g_xpw);
    cudaGetSymbolAddress((void**)&p_xp,  g_xp);

    cudaFuncSetAttribute(gemm_tf32<0>, cudaFuncAttributeMaxDynamicSharedMemorySize, GEMM_SMEM);
    cudaFuncSetAttribute(gemm_tf32<2>, cudaFuncAttributeMaxDynamicSharedMemorySize, GEMM_SMEM);
    cudaFuncSetAttribute(scan_kernel,  cudaFuncAttributeMaxDynamicSharedMemorySize, SCAN_SMEM);

    // 0) fused weight prep (tf32 rounding; xproj padded to 128 rows)
    prep_kernel<<<(NWI + NWO + NXP) / 256, 256>>>(in_proj_w, out_proj_w, x_proj_w);
    // 1) RMSNorm (float4)
    rmsnorm_kernel<<<BL_, 256>>>(x, norm_w);
    // 2) in_proj: xz[4096,4096] = xn @ wi^T
    gemm_tf32<0><<<dim3(E2_ / 128, BL_ / 128, 1), 256, GEMM_SMEM>>>(
        p_xn, DM_, p_wi, DM_, nullptr, p_xz, E2_, DM_);
    // 3) conv + SiLU -> u (tf32-rounded), 8 t per thread
    conv_silu_kernel<<<(BL_ / 8 * 512) / 256, 256>>>(conv_w, conv_b);
    // 4) x_proj (HMMA, split-K x4, padded N=128) + reduce -> x_dbl[4096,96]
    gemm_tf32<0><<<dim3(1, BL_ / 128, 4), 256, GEMM_SMEM>>>(
        p_u, E_, p_xpw, E_, nullptr, p_xp, 128, E_ / 4);
    xproj_reduce_kernel<<<(BL_ * 96) / 256, 256>>>();
    // 5+6) selective scan with fused dt projection -> y
    scan_kernel<<<B_ * (E_ / 8), 128, SCAN_SMEM>>>(A_log, Dp, dt_proj_w, dt_proj_b);
    // 7) out_proj + residual
    gemm_tf32<2><<<dim3(DM_ / 128, BL_ / 128, 1), 256, GEMM_SMEM>>>(
        p_y, E_, p_wo, E_, x, out, DM_, E_);
}